// round 6
// baseline (speedup 1.0000x reference)
#include <cuda_runtime.h>

// Spline1DInterpolant, compact-support closed form.
// s = (x-a)*n/(b-a); ib = floor(s); f = s-ib in [0,1); g = 1-f.
// y = c[ib]*g^3 + c[ib+1]*(4-6f^2+3f^3) + c[ib+2]*(4-6g^2+3g^3) + c[ib+3]*f^3
//
// Gather optimization: the 4 coeffs are consecutive -> fetch 2 aligned float4
// blocks and select window [r..r+3] (r = ib&3) with SELs. Halves gather LDG
// wavefronts (L1tex queue term). block clamp only aliases positions whose
// weight is exactly 0 (s=n edge).

__global__ __launch_bounds__(256, 1)
void spline1d_kernel(const float* __restrict__ x,
                     const float* __restrict__ a,
                     const float* __restrict__ b,
                     const float* __restrict__ n,
                     const float4* __restrict__ c4,
                     float* __restrict__ out,
                     int B, int C4) {
    int tid = blockIdx.x * blockDim.x + threadIdx.x;
    if (tid >= B) return;

    float av = a[0];
    float inv_h = n[0] / (b[0] - av);
    float s = (x[tid] - av) * inv_h;        // s in [0, n], n = 4*C4 - 3

    int ib = __float2int_rd(s);             // floor; s >= 0 -> ib >= 0
    float f = s - (float)ib;                // [0,1)
    float g = 1.0f - f;

    float f2 = f * f, f3 = f2 * f;
    float g2 = g * g, g3 = g2 * g;

    float w0 = g3;
    float w1 = fmaf(3.0f, f3, fmaf(-6.0f, f2, 4.0f));
    float w2 = fmaf(3.0f, g3, fmaf(-6.0f, g2, 4.0f));
    float w3 = f3;

    int base = ib >> 2;                     // 0 .. C4-1 (ib <= n < 4*C4)
    int r    = ib & 3;
    int base1 = min(base + 1, C4 - 1);      // clamp: aliased lanes have weight 0

    float4 q0 = c4[base];
    float4 q1 = c4[base1];

    // window[p] = c[4*base + p], p in 0..6 used; select positions r..r+3
    float d0 = (r == 0) ? q0.x : (r == 1) ? q0.y : (r == 2) ? q0.z : q0.w;
    float d1 = (r == 0) ? q0.y : (r == 1) ? q0.z : (r == 2) ? q0.w : q1.x;
    float d2 = (r == 0) ? q0.z : (r == 1) ? q0.w : (r == 2) ? q1.x : q1.y;
    float d3 = (r == 0) ? q0.w : (r == 1) ? q1.x : (r == 2) ? q1.y : q1.z;

    float acc = d0 * w0;
    acc = fmaf(d1, w1, acc);
    acc = fmaf(d2, w2, acc);
    acc = fmaf(d3, w3, acc);
    out[tid] = acc;
}

extern "C" void kernel_launch(void* const* d_in, const int* in_sizes, int n_in,
                              void* d_out, int out_size) {
    const float* x = (const float*)d_in[0];
    const float* a = (const float*)d_in[1];
    const float* b = (const float*)d_in[2];
    const float* n = (const float*)d_in[3];
    const float* c = (const float*)d_in[4];
    float* out = (float*)d_out;

    int B = in_sizes[0];      // 16384
    int C = in_sizes[4];      // 4096 (divisible by 4)

    int threads = 256;
    int blocks = (B + threads - 1) / threads;   // 64
    spline1d_kernel<<<blocks, threads>>>(x, a, b, n, (const float4*)c,
                                         out, B, C >> 2);
}